// round 2
// baseline (speedup 1.0000x reference)
#include <cuda_runtime.h>
#include <math.h>

#define B_   128
#define T_   256
#define BT   32768
#define E_   300
#define DPAD 304
#define H_   512
#define G_   2048
#define L_   96

// Static scratch (allocation-free rules): ~370 MB total
__device__ float d_xf[BT * DPAD];     // gathered/padded input features
__device__ float d_xg[BT * G_];       // gate pre-activations (x-part), reused per layer
__device__ float d_hout[BT * H_];     // per-layer sequence output, reused
__device__ float d_hbuf0[B_ * H_];    // h state double buffer
__device__ float d_hbuf1[B_ * H_];
__device__ float d_c[B_ * H_];        // cell state

// ---------------------------------------------------------------------------
// Embedding gather + predicate flag concat, padded to 304 cols with zeros
// ---------------------------------------------------------------------------
__global__ void embed_kernel(const int* __restrict__ wid,
                             const int* __restrict__ pred,
                             const float* __restrict__ emb) {
    int idx = blockIdx.x * blockDim.x + threadIdx.x;
    if (idx >= BT * DPAD) return;
    int token = idx / DPAD;
    int c = idx - token * DPAD;
    float v;
    if (c < E_)       v = emb[(size_t)wid[token] * E_ + c];
    else if (c == E_) v = (float)pred[token];
    else              v = 0.f;
    d_xf[idx] = v;
}

__global__ void zero_state_kernel() {
    int idx = blockIdx.x * blockDim.x + threadIdx.x;
    if (idx < B_ * H_) { d_hbuf0[idx] = 0.f; d_c[idx] = 0.f; }
}

// ---------------------------------------------------------------------------
// C[M][2048] = A[M][lda(pad)] @ W[Kreal][2048] + bias     (64x64 tile, 4x4 micro)
// ---------------------------------------------------------------------------
__global__ void gemm_bias_kernel(const float* __restrict__ A, int lda, int kchunks, int Kreal,
                                 const float* __restrict__ W, const float* __restrict__ bias,
                                 float* __restrict__ C) {
    __shared__ __align__(16) float As[16][64];
    __shared__ __align__(16) float Bs[16][64];
    int tid = threadIdx.x;
    int g0 = blockIdx.x * 64;
    int m0 = blockIdx.y * 64;
    int tc = tid & 15, tr = tid >> 4;
    int arow = tid & 63, akq = tid >> 6;          // A loader: row, k-quad
    int bkk = tid >> 4, bg = (tid & 15) << 2;     // B loader: k, col-quad
    float acc[4][4] = {};
    for (int kc = 0; kc < kchunks; ++kc) {
        int k0 = kc << 4;
        float4 av = *(const float4*)(A + (size_t)(m0 + arow) * lda + k0 + (akq << 2));
        float4 bv = make_float4(0.f, 0.f, 0.f, 0.f);
        int bk = k0 + bkk;
        if (bk < Kreal) bv = *(const float4*)(W + (size_t)bk * G_ + g0 + bg);
        __syncthreads();
        As[akq * 4 + 0][arow] = av.x;
        As[akq * 4 + 1][arow] = av.y;
        As[akq * 4 + 2][arow] = av.z;
        As[akq * 4 + 3][arow] = av.w;
        *(float4*)&Bs[bkk][bg] = bv;
        __syncthreads();
#pragma unroll
        for (int kk = 0; kk < 16; ++kk) {
            float4 a = *(const float4*)&As[kk][tr << 2];
            float4 b = *(const float4*)&Bs[kk][tc << 2];
            acc[0][0] += a.x * b.x; acc[0][1] += a.x * b.y; acc[0][2] += a.x * b.z; acc[0][3] += a.x * b.w;
            acc[1][0] += a.y * b.x; acc[1][1] += a.y * b.y; acc[1][2] += a.y * b.z; acc[1][3] += a.y * b.w;
            acc[2][0] += a.z * b.x; acc[2][1] += a.z * b.y; acc[2][2] += a.z * b.z; acc[2][3] += a.z * b.w;
            acc[3][0] += a.w * b.x; acc[3][1] += a.w * b.y; acc[3][2] += a.w * b.z; acc[3][3] += a.w * b.w;
        }
    }
    float4 bias4 = *(const float4*)(bias + g0 + (tc << 2));
#pragma unroll
    for (int i = 0; i < 4; ++i) {
        float4 o;
        o.x = acc[i][0] + bias4.x;
        o.y = acc[i][1] + bias4.y;
        o.z = acc[i][2] + bias4.z;
        o.w = acc[i][3] + bias4.w;
        *(float4*)(C + (size_t)(m0 + (tr << 2) + i) * G_ + g0 + (tc << 2)) = o;
    }
}

// ---------------------------------------------------------------------------
// One LSTM time step, fused recurrent GEMM + gates.
// Grid: 128 blocks, each owns a 4-wide u-slice (16 gate columns).
// 256 threads: thread = (rg 0..63 -> 2 rows, cu 0..3 -> u = u0+cu, all 4 gates).
// h state is double-buffered across steps (hprev read-only, hnext written).
// ---------------------------------------------------------------------------
__global__ void lstm_step_kernel(const float* __restrict__ xg,
                                 const float* __restrict__ U,
                                 const float* __restrict__ hprev,
                                 float* __restrict__ hnext,
                                 float* __restrict__ hout_l,
                                 const int* __restrict__ wid,
                                 int t) {
    __shared__ __align__(16) float hsT[32][128];   // [kk][row]
    __shared__ __align__(16) float Us[32][4][4];   // [kk][cu][gate]
    int tid = threadIdx.x;
    int u0 = blockIdx.x << 2;
    int cu = tid & 3;
    int rg = tid >> 2;        // 0..63
    int r0 = rg << 1;         // 2 rows per thread
    float acc0[4] = {0.f, 0.f, 0.f, 0.f};
    float acc1[4] = {0.f, 0.f, 0.f, 0.f};
    for (int k0 = 0; k0 < H_; k0 += 32) {
        __syncthreads();
#pragma unroll
        for (int j = 0; j < 4; ++j) {
            int idx = tid + j * 256;       // 0..1023 -> 128 rows x 8 k-quads
            int row = idx & 127;
            int kq  = idx >> 7;
            float4 v = *(const float4*)(hprev + (size_t)row * H_ + k0 + (kq << 2));
            hsT[kq * 4 + 0][row] = v.x;
            hsT[kq * 4 + 1][row] = v.y;
            hsT[kq * 4 + 2][row] = v.z;
            hsT[kq * 4 + 3][row] = v.w;
        }
        if (tid < 128) {
            int kk = tid >> 2;
            int c  = tid & 3;
            const float* up = U + (size_t)(k0 + kk) * G_ + u0 + c;
            Us[kk][c][0] = up[0];
            Us[kk][c][1] = up[512];
            Us[kk][c][2] = up[1024];
            Us[kk][c][3] = up[1536];
        }
        __syncthreads();
#pragma unroll
        for (int kk = 0; kk < 32; ++kk) {
            float2 a = *(const float2*)&hsT[kk][r0];
            float4 b = *(const float4*)&Us[kk][cu][0];
            acc0[0] += a.x * b.x; acc0[1] += a.x * b.y; acc0[2] += a.x * b.z; acc0[3] += a.x * b.w;
            acc1[0] += a.y * b.x; acc1[1] += a.y * b.y; acc1[2] += a.y * b.z; acc1[3] += a.y * b.w;
        }
    }
    int u = u0 + cu;
#pragma unroll
    for (int i = 0; i < 2; ++i) {
        int b = r0 + i;
        int token = b * T_ + t;
        const float* xgp = xg + (size_t)token * G_;
        float a0 = (i == 0) ? acc0[0] : acc1[0];
        float a1 = (i == 0) ? acc0[1] : acc1[1];
        float a2 = (i == 0) ? acc0[2] : acc1[2];
        float a3 = (i == 0) ? acc0[3] : acc1[3];
        float gi = a0 + xgp[u];
        float gf = a1 + xgp[512 + u];
        float gc = a2 + xgp[1024 + u];
        float go = a3 + xgp[1536 + u];
        float ig = 1.f / (1.f + __expf(-gi));
        float fg = 1.f / (1.f + __expf(-gf));
        float cd = tanhf(gc);
        float og = 1.f / (1.f + __expf(-go));
        float c_old = d_c[b * H_ + u];
        float h_old = hprev[b * H_ + u];
        float c_new = fg * c_old + ig * cd;
        float h_new = og * tanhf(c_new);
        if (wid[token] == 0) { c_new = c_old; h_new = h_old; }   // masked: carry
        d_c[b * H_ + u] = c_new;
        hnext[b * H_ + u] = h_new;
        hout_l[(size_t)token * H_ + u] = h_new;
    }
}

// ---------------------------------------------------------------------------
// Dense [512->96] + softmax. Block = 96 threads, 8 tokens per block.
// ---------------------------------------------------------------------------
__global__ void dense_softmax_kernel(const float* __restrict__ h,
                                     const float* __restrict__ Wd,
                                     const float* __restrict__ bd,
                                     float* __restrict__ out) {
    __shared__ __align__(16) float hs[8 * H_];
    __shared__ float red[96];
    int tid = threadIdx.x;          // 0..95 = output column
    int tok0 = blockIdx.x * 8;
    const float4* src = (const float4*)(h + (size_t)tok0 * H_);
    float4* dst = (float4*)hs;
    for (int i = tid; i < (8 * H_) / 4; i += 96) dst[i] = src[i];
    __syncthreads();
    float acc[8];
    float b0 = bd[tid];
#pragma unroll
    for (int tk = 0; tk < 8; ++tk) acc[tk] = b0;
    for (int k = 0; k < H_; ++k) {
        float w = Wd[k * L_ + tid];
#pragma unroll
        for (int tk = 0; tk < 8; ++tk) acc[tk] += hs[tk * H_ + k] * w;
    }
#pragma unroll
    for (int tk = 0; tk < 8; ++tk) {
        red[tid] = acc[tk];
        __syncthreads();
        if (tid < 32) {
            float m = fmaxf(red[tid], fmaxf(red[tid + 32], red[tid + 64]));
#pragma unroll
            for (int off = 16; off > 0; off >>= 1)
                m = fmaxf(m, __shfl_down_sync(0xffffffffu, m, off));
            if (tid == 0) red[0] = m;
        }
        __syncthreads();
        float mx = red[0];
        float e = __expf(acc[tk] - mx);
        __syncthreads();
        red[tid] = e;
        __syncthreads();
        if (tid < 32) {
            float s = red[tid] + red[tid + 32] + red[tid + 64];
#pragma unroll
            for (int off = 16; off > 0; off >>= 1)
                s += __shfl_down_sync(0xffffffffu, s, off);
            if (tid == 0) red[0] = s;
        }
        __syncthreads();
        float inv = 1.f / red[0];
        out[(size_t)(tok0 + tk) * L_ + tid] = e * inv;
        __syncthreads();
    }
}

// ---------------------------------------------------------------------------
extern "C" void kernel_launch(void* const* d_in, const int* in_sizes, int n_in,
                              void* d_out, int out_size) {
    const int*   wid  = (const int*)d_in[0];
    const int*   pred = (const int*)d_in[1];
    const float* emb  = (const float*)d_in[2];
    const float* W1   = (const float*)d_in[3];
    const float* U1   = (const float*)d_in[4];
    const float* b1   = (const float*)d_in[5];
    const float* W2   = (const float*)d_in[6];
    const float* U2   = (const float*)d_in[7];
    const float* b2   = (const float*)d_in[8];
    const float* Wd   = (const float*)d_in[9];
    const float* bd   = (const float*)d_in[10];
    float* out = (float*)d_out;

    float *xf, *xgp, *houtp, *h0, *h1;
    cudaGetSymbolAddress((void**)&xf,    d_xf);
    cudaGetSymbolAddress((void**)&xgp,   d_xg);
    cudaGetSymbolAddress((void**)&houtp, d_hout);
    cudaGetSymbolAddress((void**)&h0,    d_hbuf0);
    cudaGetSymbolAddress((void**)&h1,    d_hbuf1);

    // 1) embed + flag + pad
    embed_kernel<<<(BT * DPAD + 255) / 256, 256>>>(wid, pred, emb);

    dim3 ggrid(G_ / 64, BT / 64);
    // 2) xg = xf @ W1 + b1
    gemm_bias_kernel<<<ggrid, 256>>>(xf, DPAD, DPAD / 16, E_ + 1, W1, b1, xgp);

    // 3) LSTM layer 1
    zero_state_kernel<<<(B_ * H_ + 255) / 256, 256>>>();
    for (int t = 0; t < T_; ++t) {
        const float* hp = (t & 1) ? h1 : h0;
        float*       hn = (t & 1) ? h0 : h1;
        lstm_step_kernel<<<H_ / 4, 256>>>(xgp, U1, hp, hn, houtp, wid, t);
    }

    // 4) xg = h1seq @ W2 + b2
    gemm_bias_kernel<<<ggrid, 256>>>(houtp, H_, H_ / 16, H_, W2, b2, xgp);

    // 5) LSTM layer 2 (reuses hout buffer: step t only touches its own rows)
    zero_state_kernel<<<(B_ * H_ + 255) / 256, 256>>>();
    for (int t = 0; t < T_; ++t) {
        const float* hp = (t & 1) ? h1 : h0;
        float*       hn = (t & 1) ? h0 : h1;
        lstm_step_kernel<<<H_ / 4, 256>>>(xgp, U2, hp, hn, houtp, wid, t);
    }

    // 6) dense + softmax
    dense_softmax_kernel<<<BT / 8, 96>>>(houtp, Wd, bd, out);
}

// round 5
// speedup vs baseline: 1.1615x; 1.1615x over previous
#include <cuda_runtime.h>
#include <math.h>

#define B_   128
#define T_   256
#define BT   32768
#define E_   300
#define DPAD 304
#define H_   512
#define G_   2048
#define L_   96

#define NBLK 128
#define NTHR 128

// Static scratch
__device__ float d_xf[BT * DPAD];      // gathered/padded input features
__device__ float d_xg[BT * G_];        // gate pre-activations (x-part), reused per layer
__device__ float d_hout[BT * H_];      // per-layer sequence output, reused
__device__ float d_hT0[H_ * B_];       // h state, transposed [u][b], double buffer
__device__ float d_hT1[H_ * B_];

// grid barrier state
__device__ unsigned g_bar_cnt = 0;
__device__ volatile unsigned g_bar_gen = 0;

// ---------------------------------------------------------------------------
// f32x2 helpers
// ---------------------------------------------------------------------------
__device__ __forceinline__ unsigned long long dup2(float x) {
    unsigned long long r;
    asm("mov.b64 %0, {%1, %1};" : "=l"(r) : "f"(x));
    return r;
}
__device__ __forceinline__ unsigned long long ffma2(unsigned long long a,
                                                    unsigned long long b,
                                                    unsigned long long c) {
    unsigned long long d;
    asm("fma.rn.f32x2 %0, %1, %2, %3;" : "=l"(d) : "l"(a), "l"(b), "l"(c));
    return d;
}
__device__ __forceinline__ float2 unp2(unsigned long long v) {
    float2 f;
    asm("mov.b64 {%0, %1}, %2;" : "=f"(f.x), "=f"(f.y) : "l"(v));
    return f;
}

// cp.async helpers (16B, L2-only: also guarantees cross-SM freshness of hT)
__device__ __forceinline__ void cp_async16(void* sdst, const void* gsrc) {
    unsigned sa = (unsigned)__cvta_generic_to_shared(sdst);
    asm volatile("cp.async.cg.shared.global [%0], [%1], 16;" :: "r"(sa), "l"(gsrc));
}
#define CP_COMMIT  asm volatile("cp.async.commit_group;" ::: "memory")
#define CP_WAIT_1  asm volatile("cp.async.wait_group 1;" ::: "memory")
#define CP_WAIT_0  asm volatile("cp.async.wait_group 0;" ::: "memory")

__device__ __forceinline__ void grid_barrier() {
    __threadfence();
    __syncthreads();
    if (threadIdx.x == 0) {
        unsigned gen = g_bar_gen;
        if (atomicAdd(&g_bar_cnt, 1u) == NBLK - 1) {
            g_bar_cnt = 0;
            __threadfence();
            g_bar_gen = gen + 1;
        } else {
            while (g_bar_gen == gen) { __nanosleep(64); }
        }
        __threadfence();
    }
    __syncthreads();
}

// ---------------------------------------------------------------------------
// Embedding gather + predicate flag concat, padded to 304 cols with zeros
// ---------------------------------------------------------------------------
__global__ void embed_kernel(const int* __restrict__ wid,
                             const int* __restrict__ pred,
                             const float* __restrict__ emb) {
    int idx = blockIdx.x * blockDim.x + threadIdx.x;
    if (idx >= BT * DPAD) return;
    int token = idx / DPAD;
    int c = idx - token * DPAD;
    float v;
    if (c < E_)       v = emb[(size_t)wid[token] * E_ + c];
    else if (c == E_) v = (float)pred[token];
    else              v = 0.f;
    d_xf[idx] = v;
}

// ---------------------------------------------------------------------------
// C[M][2048] = A[M][lda] @ W[Kreal][2048] + bias  — 64x64 tile, f32x2 micro
// ---------------------------------------------------------------------------
__global__ void gemm_bias_kernel(const float* __restrict__ A, int lda, int kchunks, int Kreal,
                                 const float* __restrict__ W, const float* __restrict__ bias,
                                 float* __restrict__ C) {
    __shared__ __align__(16) float As[16][64];
    __shared__ __align__(16) unsigned long long Bsd[16][64];   // dup'd pairs
    int tid = threadIdx.x;
    int g0 = blockIdx.x * 64;
    int m0 = blockIdx.y * 64;
    int tc = tid & 15, tr = tid >> 4;
    int arow = tid & 63, akq = tid >> 6;          // A loader: row, k-quad
    int bkk = tid >> 4, bg = (tid & 15) << 2;     // B loader: k, col-quad
    unsigned long long accP[2][4];
#pragma unroll
    for (int p = 0; p < 2; ++p)
#pragma unroll
        for (int j = 0; j < 4; ++j) accP[p][j] = 0ull;

    for (int kc = 0; kc < kchunks; ++kc) {
        int k0 = kc << 4;
        float4 av = *(const float4*)(A + (size_t)(m0 + arow) * lda + k0 + (akq << 2));
        float4 bv = make_float4(0.f, 0.f, 0.f, 0.f);
        int bk = k0 + bkk;
        if (bk < Kreal) bv = *(const float4*)(W + (size_t)bk * G_ + g0 + bg);
        __syncthreads();
        As[akq * 4 + 0][arow] = av.x;
        As[akq * 4 + 1][arow] = av.y;
        As[akq * 4 + 2][arow] = av.z;
        As[akq * 4 + 3][arow] = av.w;
        Bsd[bkk][bg + 0] = dup2(bv.x);
        Bsd[bkk][bg + 1] = dup2(bv.y);
        Bsd[bkk][bg + 2] = dup2(bv.z);
        Bsd[bkk][bg + 3] = dup2(bv.w);
        __syncthreads();
#pragma unroll
        for (int kk = 0; kk < 16; ++kk) {
            unsigned long long a01 = *(const unsigned long long*)&As[kk][tr << 2];
            unsigned long long a23 = *(const unsigned long long*)(&As[kk][tr << 2] + 2);
            const ulonglong2* bp = (const ulonglong2*)&Bsd[kk][tc << 2];
            ulonglong2 b01 = bp[0];
            ulonglong2 b23 = bp[1];
            accP[0][0] = ffma2(a01, b01.x, accP[0][0]);
            accP[1][0] = ffma2(a23, b01.x, accP[1][0]);
            accP[0][1] = ffma2(a01, b01.y, accP[0][1]);
            accP[1][1] = ffma2(a23, b01.y, accP[1][1]);
            accP[0][2] = ffma2(a01, b23.x, accP[0][2]);
            accP[1][2] = ffma2(a23, b23.x, accP[1][2]);
            accP[0][3] = ffma2(a01, b23.y, accP[0][3]);
            accP[1][3] = ffma2(a23, b23.y, accP[1][3]);
        }
    }
    float4 bias4 = *(const float4*)(bias + g0 + (tc << 2));
#pragma unroll
    for (int p = 0; p < 2; ++p) {
        float2 c0 = unp2(accP[p][0]);
        float2 c1 = unp2(accP[p][1]);
        float2 c2 = unp2(accP[p][2]);
        float2 c3 = unp2(accP[p][3]);
        float4 lo = make_float4(c0.x + bias4.x, c1.x + bias4.y, c2.x + bias4.z, c3.x + bias4.w);
        float4 hi = make_float4(c0.y + bias4.x, c1.y + bias4.y, c2.y + bias4.z, c3.y + bias4.w);
        *(float4*)(C + (size_t)(m0 + (tr << 2) + 2 * p)     * G_ + g0 + (tc << 2)) = lo;
        *(float4*)(C + (size_t)(m0 + (tr << 2) + 2 * p + 1) * G_ + g0 + (tc << 2)) = hi;
    }
}

// ---------------------------------------------------------------------------
// Persistent masked-LSTM layer. 128 blocks x 128 threads; block owns u-slice
// u0..u0+3 (16 gate cols). U pre-dup'd in smem once. h transposed [u][b] in
// global, double-buffered across steps; grid barrier per step. c and carried
// h live in registers. Thread = (rg: 4 rows, cu: 1 u, 4 gates).
// READ  xg rows: layer0 -> b*T + t (token-major, from embed GEMM)
//                layer1 -> t*B + b (from layer-0 output order)
// WRITE hout rows: ALWAYS t*B + b (step-major; what layer1/dense consume)
// ---------------------------------------------------------------------------
__global__ void __launch_bounds__(NTHR, 1)
lstm_persistent_kernel(const float* __restrict__ xg,
                       const float* __restrict__ U,
                       float* __restrict__ hTa,
                       float* __restrict__ hTb,
                       float* __restrict__ hout_l,
                       const int* __restrict__ wid,
                       int layer) {
    extern __shared__ unsigned char smem_raw[];
    unsigned long long (*Usd)[16] = (unsigned long long(*)[16])smem_raw;   // 64KB
    float* hsA = (float*)(smem_raw + 65536);                               // 16KB
    float* hsB = hsA + 32 * 128;                                           // 16KB

    const int tid = threadIdx.x;
    const int u0 = blockIdx.x << 2;
    const int cu = tid & 3;
    const int rg = tid >> 2;          // 0..31
    const int r0 = rg << 2;           // 4 rows per thread
    const int u  = u0 + cu;

    // One-time: load + duplicate U slice into smem: Usd[k][c*4+g] = dup(U[k][g*512+u0+c])
    for (int i = tid; i < H_ * 4; i += NTHR) {
        int k = i >> 2;
        int c = i & 3;
        const float* up = U + (size_t)k * G_ + u0 + c;
        Usd[k][c * 4 + 0] = dup2(up[0]);
        Usd[k][c * 4 + 1] = dup2(up[512]);
        Usd[k][c * 4 + 2] = dup2(up[1024]);
        Usd[k][c * 4 + 3] = dup2(up[1536]);
    }
    // zero our slice of hT0 (4 u-rows x 128 b)
    *(float4*)(hTa + (size_t)u * B_ + r0) = make_float4(0.f, 0.f, 0.f, 0.f);
    grid_barrier();

    float cst[4]  = {0.f, 0.f, 0.f, 0.f};
    float hcar[4] = {0.f, 0.f, 0.f, 0.f};
    const float* hTp = hTa;
    float*       hTn = hTb;

    for (int t = 0; t < T_; ++t) {
        // prefetch xg gate inputs + mask for our 4 rows (hidden behind k-loop)
        float xv[4][4];
        int   wv[4];
#pragma unroll
        for (int i = 0; i < 4; ++i) {
            int b = r0 + i;
            int tok_read = (layer == 0) ? (b * T_ + t) : (t * B_ + b);
            wv[i] = __ldg(&wid[b * T_ + t]);
            const float* xp = xg + (size_t)tok_read * G_ + u;
            xv[i][0] = __ldg(xp);
            xv[i][1] = __ldg(xp + 512);
            xv[i][2] = __ldg(xp + 1024);
            xv[i][3] = __ldg(xp + 1536);
        }

        unsigned long long accA[4] = {0ull, 0ull, 0ull, 0ull};   // rows r0,r0+1
        unsigned long long accB[4] = {0ull, 0ull, 0ull, 0ull};   // rows r0+2,r0+3

        // stage chunk 0
#pragma unroll
        for (int j = 0; j < 8; ++j) {
            int idx = tid + j * NTHR;
            cp_async16((float4*)hsA + idx, (const float4*)hTp + idx);
        }
        CP_COMMIT;

        for (int ch = 0; ch < 16; ++ch) {
            float* cur = (ch & 1) ? hsB : hsA;
            float* nxt = (ch & 1) ? hsA : hsB;
            if (ch < 15) {
                const float4* src = (const float4*)(hTp + (ch + 1) * 32 * B_);
#pragma unroll
                for (int j = 0; j < 8; ++j) {
                    int idx = tid + j * NTHR;
                    cp_async16((float4*)nxt + idx, src + idx);
                }
                CP_COMMIT;
                CP_WAIT_1;
            } else {
                CP_WAIT_0;
            }
            __syncthreads();
            const unsigned long long(*ud)[16] = &Usd[ch * 32];
#pragma unroll
            for (int kk = 0; kk < 32; ++kk) {
                const float* hrow = cur + kk * B_ + r0;
                unsigned long long a01 = *(const unsigned long long*)(hrow);
                unsigned long long a23 = *(const unsigned long long*)(hrow + 2);
                const ulonglong2* bp = (const ulonglong2*)&ud[kk][cu << 2];
                ulonglong2 b01 = bp[0];
                ulonglong2 b23 = bp[1];
                accA[0] = ffma2(a01, b01.x, accA[0]);
                accB[0] = ffma2(a23, b01.x, accB[0]);
                accA[1] = ffma2(a01, b01.y, accA[1]);
                accB[1] = ffma2(a23, b01.y, accB[1]);
                accA[2] = ffma2(a01, b23.x, accA[2]);
                accB[2] = ffma2(a23, b23.x, accB[2]);
                accA[3] = ffma2(a01, b23.y, accA[3]);
                accB[3] = ffma2(a23, b23.y, accB[3]);
            }
            __syncthreads();
        }

        // gate math, 4 rows
        float2 gA0 = unp2(accA[0]), gA1 = unp2(accA[1]), gA2 = unp2(accA[2]), gA3 = unp2(accA[3]);
        float2 gB0 = unp2(accB[0]), gB1 = unp2(accB[1]), gB2 = unp2(accB[2]), gB3 = unp2(accB[3]);
        float ai[4] = {gA0.x, gA0.y, gB0.x, gB0.y};
        float af[4] = {gA1.x, gA1.y, gB1.x, gB1.y};
        float ac[4] = {gA2.x, gA2.y, gB2.x, gB2.y};
        float ao[4] = {gA3.x, gA3.y, gB3.x, gB3.y};
        float hn4[4];
#pragma unroll
        for (int i = 0; i < 4; ++i) {
            float gi = ai[i] + xv[i][0];
            float gf = af[i] + xv[i][1];
            float gc = ac[i] + xv[i][2];
            float go = ao[i] + xv[i][3];
            float ig = 1.f / (1.f + __expf(-gi));
            float fg = 1.f / (1.f + __expf(-gf));
            float cd = tanhf(gc);
            float og = 1.f / (1.f + __expf(-go));
            float cn = fg * cst[i] + ig * cd;
            float hn = og * tanhf(cn);
            if (wv[i] == 0) { cn = cst[i]; hn = hcar[i]; }   // masked: carry
            cst[i] = cn;
            hcar[i] = hn;
            hn4[i] = hn;
            int b = r0 + i;
            int tok_write = t * B_ + b;        // ALWAYS step-major
            hout_l[(size_t)tok_write * H_ + u] = hn;
        }
        *(float4*)(hTn + (size_t)u * B_ + r0) = make_float4(hn4[0], hn4[1], hn4[2], hn4[3]);

        grid_barrier();
        const float* tp = hTp; hTp = hTn; hTn = (float*)tp;
    }
}

// ---------------------------------------------------------------------------
// Dense [512->96] + softmax. Source rows are [t*128+b]; output rows [b*256+t].
// ---------------------------------------------------------------------------
__global__ void dense_softmax_kernel(const float* __restrict__ h,
                                     const float* __restrict__ Wd,
                                     const float* __restrict__ bd,
                                     float* __restrict__ out) {
    __shared__ __align__(16) float hs[8 * H_];
    __shared__ float red[96];
    int tid = threadIdx.x;          // 0..95 = output column
    int tok0 = blockIdx.x * 8;
    const float4* src = (const float4*)(h + (size_t)tok0 * H_);
    float4* dst = (float4*)hs;
    for (int i = tid; i < (8 * H_) / 4; i += 96) dst[i] = src[i];
    __syncthreads();
    float acc[8];
    float b0 = bd[tid];
#pragma unroll
    for (int tk = 0; tk < 8; ++tk) acc[tk] = b0;
    for (int k = 0; k < H_; ++k) {
        float w = Wd[k * L_ + tid];
#pragma unroll
        for (int tk = 0; tk < 8; ++tk) acc[tk] += hs[tk * H_ + k] * w;
    }
#pragma unroll
    for (int tk = 0; tk < 8; ++tk) {
        red[tid] = acc[tk];
        __syncthreads();
        if (tid < 32) {
            float m = fmaxf(red[tid], fmaxf(red[tid + 32], red[tid + 64]));
#pragma unroll
            for (int off = 16; off > 0; off >>= 1)
                m = fmaxf(m, __shfl_down_sync(0xffffffffu, m, off));
            if (tid == 0) red[0] = m;
        }
        __syncthreads();
        float mx = red[0];
        float e = __expf(acc[tk] - mx);
        __syncthreads();
        red[tid] = e;
        __syncthreads();
        if (tid < 32) {
            float s = red[tid] + red[tid + 32] + red[tid + 64];
#pragma unroll
            for (int off = 16; off > 0; off >>= 1)
                s += __shfl_down_sync(0xffffffffu, s, off);
            if (tid == 0) red[0] = s;
        }
        __syncthreads();
        float inv = 1.f / red[0];
        int sr = tok0 + tk;                 // t*128 + b
        int tt = sr >> 7, bb = sr & 127;
        out[(size_t)(bb * T_ + tt) * L_ + tid] = e * inv;
        __syncthreads();
    }
}

// ---------------------------------------------------------------------------
extern "C" void kernel_launch(void* const* d_in, const int* in_sizes, int n_in,
                              void* d_out, int out_size) {
    const int*   wid  = (const int*)d_in[0];
    const int*   pred = (const int*)d_in[1];
    const float* emb  = (const float*)d_in[2];
    const float* W1   = (const float*)d_in[3];
    const float* U1   = (const float*)d_in[4];
    const float* b1   = (const float*)d_in[5];
    const float* W2   = (const float*)d_in[6];
    const float* U2   = (const float*)d_in[7];
    const float* b2   = (const float*)d_in[8];
    const float* Wd   = (const float*)d_in[9];
    const float* bd   = (const float*)d_in[10];
    float* out = (float*)d_out;

    float *xf, *xgp, *houtp, *hA, *hB;
    cudaGetSymbolAddress((void**)&xf,    d_xf);
    cudaGetSymbolAddress((void**)&xgp,   d_xg);
    cudaGetSymbolAddress((void**)&houtp, d_hout);
    cudaGetSymbolAddress((void**)&hA,    d_hT0);
    cudaGetSymbolAddress((void**)&hB,    d_hT1);

    static int smem_set = 0;
    if (!smem_set) {
        cudaFuncSetAttribute(lstm_persistent_kernel,
                             cudaFuncAttributeMaxDynamicSharedMemorySize, 98304);
        smem_set = 1;
    }

    // 1) embed + flag + pad
    embed_kernel<<<(BT * DPAD + 255) / 256, 256>>>(wid, pred, emb);

    dim3 ggrid(G_ / 64, BT / 64);
    // 2) xg = xf @ W1 + b1
    gemm_bias_kernel<<<ggrid, 256>>>(xf, DPAD, DPAD / 16, E_ + 1, W1, b1, xgp);

    // 3) LSTM layer 1 (persistent; reads xg rows b*T+t, writes hout rows t*B+b)
    lstm_persistent_kernel<<<NBLK, NTHR, 98304>>>(xgp, U1, hA, hB, houtp, wid, 0);

    // 4) xg = h1seq @ W2 + b2  (rows stay t*B+b)
    gemm_bias_kernel<<<ggrid, 256>>>(houtp, H_, H_ / 16, H_, W2, b2, xgp);

    // 5) LSTM layer 2 (persistent; reads and writes rows t*B+b)
    lstm_persistent_kernel<<<NBLK, NTHR, 98304>>>(xgp, U2, hA, hB, houtp, wid, 1);

    // 6) dense + softmax (permutes rows back to [b*256+t])
    dense_softmax_kernel<<<BT / 8, 96>>>(houtp, Wd, bd, out);
}